// round 6
// baseline (speedup 1.0000x reference)
#include <cuda_runtime.h>
#include <cuda_fp16.h>
#include <cstdint>
#include <math.h>

#define CC 256          // channels
#define GG_MAX 4096     // graphs
#define N_MAX 500000    // nodes

__device__ __align__(16) __half g_Wth[CC * CC];   // W1a^T fp16: [n][k]
__device__ float        g_sumb[GG_MAX * CC];
__device__ float        g_attb[GG_MAX * CC];
__device__ unsigned int g_maxu[GG_MAX * CC];
__device__ int          g_cnt[GG_MAX];
__device__ float        g_comb[GG_MAX * 3 * CC];
__device__ float        g_hidden[GG_MAX * CC];
__device__ int          g_is64;

// ---------------------------------------------------------------------------
// helpers
// ---------------------------------------------------------------------------
__device__ __forceinline__ uint32_t smem_u32(const void* p) {
    uint32_t a;
    asm("{ .reg .u64 t; cvta.to.shared.u64 t, %1; cvt.u32.u64 %0, t; }" : "=r"(a) : "l"(p));
    return a;
}

#define LDMX4(r0, r1, r2, r3, addr) \
    asm volatile("ldmatrix.sync.aligned.m8n8.x4.shared.b16 {%0,%1,%2,%3}, [%4];" \
        : "=r"(r0), "=r"(r1), "=r"(r2), "=r"(r3) : "r"(addr))

__device__ __forceinline__ void mma_f16(float* c, const uint32_t* a, uint32_t b0, uint32_t b1) {
    asm volatile(
        "mma.sync.aligned.m16n8k16.row.col.f32.f16.f16.f32 "
        "{%0,%1,%2,%3}, {%4,%5,%6,%7}, {%8,%9}, {%0,%1,%2,%3};"
        : "+f"(c[0]), "+f"(c[1]), "+f"(c[2]), "+f"(c[3])
        : "r"(a[0]), "r"(a[1]), "r"(a[2]), "r"(a[3]), "r"(b0), "r"(b1));
}

#define CP_COMMIT() asm volatile("cp.async.commit_group;" ::: "memory")
#define CP_WAIT2()  asm volatile("cp.async.wait_group 2;" ::: "memory")

// monotone float<->uint for atomicMax on signed floats
__device__ __forceinline__ unsigned int fkey(float f) {
    unsigned int u = __float_as_uint(f);
    return (u & 0x80000000u) ? ~u : (u | 0x80000000u);
}
__device__ __forceinline__ float finv(unsigned int k) {
    unsigned int u = (k & 0x80000000u) ? (k ^ 0x80000000u) : ~k;
    return __uint_as_float(u);
}
#define KEY_NEG_INF 0x007FFFFFu   // fkey(-inf)

// ---------------------------------------------------------------------------
// batch dtype detection (int32 vs int64 view; sorted-ness discriminates)
// ---------------------------------------------------------------------------
__global__ void k0_init() { g_is64 = 0; }
__global__ void k0_detect(const int* __restrict__ b32, int N) {
    int i = blockIdx.x * blockDim.x + threadIdx.x;
    if (i < N - 1) {
        int a = b32[i], b = b32[i + 1];
        if (a > b || a < 0 || b < 0) g_is64 = 1;
    }
}
__device__ __forceinline__ long long bval(const void* b, int i) {
    if (g_is64) return ((const long long*)b)[i];
    return (long long)((const int*)b)[i];
}

// ---------------------------------------------------------------------------
// W1a -> transposed fp16;  pooling accumulator init
// ---------------------------------------------------------------------------
__global__ void k_wt(const float* __restrict__ W1a) {
    int n = blockIdx.x, k = threadIdx.x;
    g_Wth[n * CC + k] = __float2half(W1a[k * CC + n]);
}
__global__ void k_initbuf() {
    int i = blockIdx.x * blockDim.x + threadIdx.x;
    if (i < GG_MAX * CC) { g_sumb[i] = 0.f; g_attb[i] = 0.f; g_maxu[i] = KEY_NEG_INF; }
    if (i < GG_MAX) g_cnt[i] = 0;
}

// ---------------------------------------------------------------------------
// K1 (fused): attention MLP (fp16 mma) + segment pooling, persistent CTAs.
// B fragments live in REGISTERS for the whole kernel (warp: n32 slice,
// 16 ks x 2 frags x 4 regs = 128). B smem region is overlaid with the
// 4-stage A32 cp.async ring (B only needed in smem during prologue).
// Per tile (32 nodes): wait ring stage -> convert fp32->fp16 (swizzled) ->
// prefetch stage+3 -> mma (m32 x n32/warp x k256) -> relu.W2a epilogue ->
// sigmoid -> pooling from resident fp32 stage, per-segment-run RED atomics.
// ---------------------------------------------------------------------------
#define TILE_M    32
#define RING_OFF  0            // 4 x 32768 = 131072 (also B fill region, 128KB)
#define STG_BYTES 32768
#define A16_OFF   131072       // 16384
#define SB1_OFF   147456       // 1024
#define SW2_OFF   148480       // 1024
#define PBUF_OFF  149504       // 8*32 floats = 1024
#define SAW_OFF   150528       // 32 floats
#define SSEG_OFF  150656       // 32 ints
#define K1_SMEM   150784

__device__ __forceinline__ void k1_load_stage(uint32_t sb, const float* __restrict__ x,
                                              int m0, int N, int s) {
    const int tid = threadIdx.x;
    #pragma unroll
    for (int u = 0; u < 8; ++u) {
        int idx = tid + u * 256;            // 2048 16B-chunks: 32 rows x 64 f4
        int row = idx >> 6, c4 = idx & 63;
        int node = m0 + row;
        const float* src = x + (size_t)(node < N ? node : 0) * CC + c4 * 4;
        uint32_t dst = sb + RING_OFF + s * STG_BYTES + row * 1024 + c4 * 16;
        uint32_t sz = (node < N) ? 16u : 0u;
        asm volatile("cp.async.cg.shared.global [%0], [%1], 16, %2;"
                     :: "r"(dst), "l"(src), "r"(sz));
    }
}

__global__ void __launch_bounds__(256, 1) k1_fused(
    const float* __restrict__ x, const void* __restrict__ batch,
    const float* __restrict__ b1a, const float* __restrict__ W2a,
    const float* __restrict__ b2a, int N, int nTiles)
{
    extern __shared__ char sm[];
    const uint32_t sb = smem_u32(sm);
    float* sB1  = (float*)(sm + SB1_OFF);
    float* sW2  = (float*)(sm + SW2_OFF);
    float* pbuf = (float*)(sm + PBUF_OFF);
    float* saw  = (float*)(sm + SAW_OFF);
    int*   sseg = (int*)(sm + SSEG_OFF);

    const int tid  = threadIdx.x;
    const int lane = tid & 31;
    const int w    = tid >> 5;
    const int ncol0 = w * 32;

    sB1[tid] = b1a[tid];
    sW2[tid] = W2a[tid];
    const float b2 = b2a[0];

    // --- prologue: fill B smem (overlaid on ring), load B frags to regs ---
    #pragma unroll 4
    for (int it = 0; it < 32; ++it) {
        int idx = tid + it * 256;          // 8192 16B-chunks (256 rows x 512B)
        int row = idx >> 5, c = idx & 31;
        uint4 v = *(const uint4*)(g_Wth + (size_t)row * CC + c * 8);
        *(uint4*)(sm + RING_OFF + row * 512 + ((c ^ (row & 7)) << 4)) = v;
    }
    __syncthreads();

    const int lrow   = lane & 15;
    const int lchunk = lane >> 4;
    const int qr = lane >> 2, qc = lane & 3;

    uint32_t breg[16][2][4];
    #pragma unroll
    for (int ks = 0; ks < 16; ++ks) {
        const int kc = ks * 2 + lchunk;
        #pragma unroll
        for (int bq = 0; bq < 2; ++bq) {
            int nr = ncol0 + bq * 16 + lrow;
            uint32_t ad = sb + RING_OFF + nr * 512 + ((kc ^ (nr & 7)) << 4);
            LDMX4(breg[ks][bq][0], breg[ks][bq][1], breg[ks][bq][2], breg[ks][bq][3], ad);
        }
    }
    __syncthreads();   // B smem region free -> becomes A ring

    // --- prime 3 ring stages ---
    #pragma unroll
    for (int j = 0; j < 3; ++j) {
        int tj = blockIdx.x + j * gridDim.x;
        if (tj < nTiles) k1_load_stage(sb, x, tj * TILE_M, N, j);
        CP_COMMIT();
    }

    int i = 0;
    for (int t = blockIdx.x; t < nTiles; t += gridDim.x, ++i) {
        const int s  = i & 3;
        const int m0 = t * TILE_M;
        const int rows = (N - m0 < TILE_M) ? (N - m0) : TILE_M;

        CP_WAIT2();
        __syncthreads();          // stage s resident for all threads

        // convert A32[s] -> A16 (swizzled fp16), load tile seg ids
        #pragma unroll
        for (int it = 0; it < 4; ++it) {
            int idx = tid + it * 256;      // 1024 fp16 16B-chunks: 32 rows x 32
            int row = idx >> 5, c = idx & 31;
            const float4* src = (const float4*)(sm + RING_OFF + s * STG_BYTES + row * 1024 + c * 32);
            float4 v0 = src[0], v1 = src[1];
            __half2 h0 = __floats2half2_rn(v0.x, v0.y), h1 = __floats2half2_rn(v0.z, v0.w);
            __half2 h2 = __floats2half2_rn(v1.x, v1.y), h3 = __floats2half2_rn(v1.z, v1.w);
            uint4 u;
            u.x = *(uint32_t*)&h0; u.y = *(uint32_t*)&h1;
            u.z = *(uint32_t*)&h2; u.w = *(uint32_t*)&h3;
            *(uint4*)(sm + A16_OFF + row * 512 + ((c ^ (row & 7)) << 4)) = u;
        }
        if (tid < TILE_M)
            sseg[tid] = (m0 + tid < N) ? (int)bval(batch, m0 + tid) : -1;
        __syncthreads();          // A16 + sseg ready

        // prefetch stage i+3 (overlaps mma below)
        {
            int tn = t + 3 * gridDim.x;
            if (tn < nTiles) k1_load_stage(sb, x, tn * TILE_M, N, (i + 3) & 3);
            CP_COMMIT();
        }

        // mma: warp computes m32 x n32 over k256; B from registers
        float acc[2][4][4];
        #pragma unroll
        for (int mt = 0; mt < 2; ++mt)
            #pragma unroll
            for (int j = 0; j < 4; ++j) {
                acc[mt][j][0] = 0.f; acc[mt][j][1] = 0.f;
                acc[mt][j][2] = 0.f; acc[mt][j][3] = 0.f;
            }
        #pragma unroll
        for (int ks = 0; ks < 16; ++ks) {
            const int kc = ks * 2 + lchunk;
            uint32_t a[2][4];
            #pragma unroll
            for (int mt = 0; mt < 2; ++mt) {
                int row = mt * 16 + lrow;
                uint32_t ad = sb + A16_OFF + row * 512 + ((kc ^ (row & 7)) << 4);
                LDMX4(a[mt][0], a[mt][1], a[mt][2], a[mt][3], ad);
            }
            #pragma unroll
            for (int mt = 0; mt < 2; ++mt)
                #pragma unroll
                for (int bq = 0; bq < 2; ++bq) {
                    mma_f16(acc[mt][2 * bq],     a[mt], breg[ks][bq][0], breg[ks][bq][2]);
                    mma_f16(acc[mt][2 * bq + 1], a[mt], breg[ks][bq][1], breg[ks][bq][3]);
                }
        }

        // epilogue: relu -> dot W2a (warp's n32 slice)
        float p[4] = {0.f, 0.f, 0.f, 0.f};   // rows qr, qr+8, 16+qr, 24+qr
        #pragma unroll
        for (int mt = 0; mt < 2; ++mt)
            #pragma unroll
            for (int j = 0; j < 4; ++j) {
                int col = ncol0 + j * 8 + qc * 2;
                float bA = sB1[col], bB = sB1[col + 1];
                float wA = sW2[col], wB = sW2[col + 1];
                p[mt * 2]     += fmaxf(acc[mt][j][0] + bA, 0.f) * wA
                               + fmaxf(acc[mt][j][1] + bB, 0.f) * wB;
                p[mt * 2 + 1] += fmaxf(acc[mt][j][2] + bA, 0.f) * wA
                               + fmaxf(acc[mt][j][3] + bB, 0.f) * wB;
            }
        #pragma unroll
        for (int j = 0; j < 4; ++j) {
            p[j] += __shfl_xor_sync(0xffffffffu, p[j], 1);
            p[j] += __shfl_xor_sync(0xffffffffu, p[j], 2);
        }
        if (qc == 0) {
            pbuf[w * 32 + qr]      = p[0];
            pbuf[w * 32 + qr + 8]  = p[1];
            pbuf[w * 32 + qr + 16] = p[2];
            pbuf[w * 32 + qr + 24] = p[3];
        }
        __syncthreads();
        if (tid < 32) {
            float ssum = 0.f;
            #pragma unroll
            for (int k = 0; k < 8; ++k) ssum += pbuf[k * 32 + tid];
            saw[tid] = 1.f / (1.f + expf(-(ssum + b2)));
        }
        __syncthreads();          // saw ready

        // --- pooling: thread owns one channel; per-segment runs; RED atomics ---
        {
            const int c = tid;
            int rs = 0;
            while (rs < rows) {
                int seg = sseg[rs];
                int re = rs + 1;
                while (re < rows && sseg[re] == seg) ++re;

                float psum = 0.f, patt = 0.f, pmx = -INFINITY;
                for (int row = rs; row < re; ++row) {
                    float v = *(const float*)(sm + RING_OFF + s * STG_BYTES + row * 1024 + c * 4);
                    float aw = saw[row];
                    psum += v;
                    patt = fmaf(v, aw, patt);
                    pmx = fmaxf(pmx, v);
                }
                size_t o = (size_t)seg * CC + c;
                atomicAdd(&g_sumb[o], psum);
                atomicAdd(&g_attb[o], patt);
                atomicMax(&g_maxu[o], fkey(pmx));
                if (tid == 0) atomicAdd(&g_cnt[seg], re - rs);
                rs = re;
            }
        }
    }
}

// ---------------------------------------------------------------------------
// fixup: assemble combined = [att | mean | max]  (empty segments -> 0)
// ---------------------------------------------------------------------------
__global__ void k_fix() {
    int g = blockIdx.x, c = threadIdx.x;
    int cnt = g_cnt[g];
    size_t o = (size_t)g * CC + c;
    float* comb = g_comb + (size_t)g * (3 * CC);
    comb[c]          = g_attb[o];
    comb[CC + c]     = g_sumb[o] / fmaxf((float)cnt, 1.f);
    comb[2 * CC + c] = (cnt > 0) ? finv(g_maxu[o]) : 0.f;
}

// ---------------------------------------------------------------------------
// K3: fp32 tiled GEMM with bias (+optional relu). 64x64 tile, 256 threads.
// ---------------------------------------------------------------------------
template <bool RELU>
__global__ void __launch_bounds__(256) k3_gemm(
    const float* __restrict__ A, const float* __restrict__ B,
    const float* __restrict__ bias, float* __restrict__ Out,
    int M, int K, int Nn)
{
    __shared__ float sA[16][68];
    __shared__ float sB[16][68];
    const int t  = threadIdx.x;
    const int tx = t & 15, ty = t >> 4;
    const int m0 = blockIdx.y * 64, n0 = blockIdx.x * 64;
    float acc[4][4] = {};

    for (int kt = 0; kt < K; kt += 16) {
        #pragma unroll
        for (int i = 0; i < 4; ++i) {
            int idx = t + i * 256;
            int m = idx >> 4, k = idx & 15;
            sA[k][m] = A[(size_t)(m0 + m) * K + kt + k];
        }
        #pragma unroll
        for (int i = 0; i < 4; ++i) {
            int idx = t + i * 256;
            int k = idx >> 6, n = idx & 63;
            sB[k][n] = B[(size_t)(kt + k) * Nn + n0 + n];
        }
        __syncthreads();
        #pragma unroll
        for (int kk = 0; kk < 16; ++kk) {
            float4 a4 = *(const float4*)&sA[kk][ty * 4];
            float4 b4 = *(const float4*)&sB[kk][tx * 4];
            float av[4] = {a4.x, a4.y, a4.z, a4.w};
            float bv[4] = {b4.x, b4.y, b4.z, b4.w};
            #pragma unroll
            for (int i = 0; i < 4; ++i)
                #pragma unroll
                for (int j = 0; j < 4; ++j)
                    acc[i][j] = fmaf(av[i], bv[j], acc[i][j]);
        }
        __syncthreads();
    }

    #pragma unroll
    for (int i = 0; i < 4; ++i) {
        int m = m0 + ty * 4 + i;
        #pragma unroll
        for (int j = 0; j < 4; ++j) {
            int n = n0 + tx * 4 + j;
            float v = acc[i][j] + bias[n];
            if (RELU) v = fmaxf(v, 0.f);
            Out[(size_t)m * Nn + n] = v;
        }
    }
}

// ---------------------------------------------------------------------------
// launch
// ---------------------------------------------------------------------------
extern "C" void kernel_launch(void* const* d_in, const int* in_sizes, int n_in,
                              void* d_out, int out_size)
{
    const float* x     = (const float*)d_in[0];
    const void*  batch = d_in[1];
    const float* W1a   = (const float*)d_in[2];
    const float* b1a   = (const float*)d_in[3];
    const float* W2a   = (const float*)d_in[4];
    const float* b2a   = (const float*)d_in[5];
    const float* W1f   = (const float*)d_in[6];
    const float* b1f   = (const float*)d_in[7];
    const float* W2f   = (const float*)d_in[8];
    const float* b2f   = (const float*)d_in[9];
    float* out = (float*)d_out;

    const int N = in_sizes[0] / CC;
    const int G = out_size / CC;

    float *comb_ptr = nullptr, *hid_ptr = nullptr;
    cudaGetSymbolAddress((void**)&comb_ptr, g_comb);
    cudaGetSymbolAddress((void**)&hid_ptr, g_hidden);

    cudaFuncSetAttribute(k1_fused, cudaFuncAttributeMaxDynamicSharedMemorySize, K1_SMEM);

    k0_init<<<1, 1>>>();
    k0_detect<<<(N + 255) / 256, 256>>>((const int*)batch, N);
    k_wt<<<CC, CC>>>(W1a);
    k_initbuf<<<(GG_MAX * CC) / 256, 256>>>();

    const int nTiles = (N + TILE_M - 1) / TILE_M;
    const int grid = nTiles < 148 ? nTiles : 148;
    k1_fused<<<grid, 256, K1_SMEM>>>(x, batch, b1a, W2a, b2a, N, nTiles);
    k_fix<<<G, 256>>>();
    k3_gemm<true ><<<dim3(CC / 64, G / 64), 256>>>(comb_ptr, W1f, b1f, hid_ptr, G, 3 * CC, CC);
    k3_gemm<false><<<dim3(CC / 64, G / 64), 256>>>(hid_ptr,  W2f, b2f, out,     G, CC,     CC);
}

// round 7
// speedup vs baseline: 1.1972x; 1.1972x over previous
#include <cuda_runtime.h>
#include <cuda_fp16.h>
#include <cstdint>
#include <math.h>

#define CC 256          // channels
#define GG_MAX 4096     // graphs
#define N_MAX 500000    // nodes

__device__ float g_aw[N_MAX + 256];
__device__ __align__(16) __half g_Wth[CC * CC];   // W1a^T fp16: [n][k]
__device__ float g_comb[GG_MAX * 3 * CC];
__device__ float g_hidden[GG_MAX * CC];
__device__ int   g_is64;

// ---------------------------------------------------------------------------
// helpers
// ---------------------------------------------------------------------------
__device__ __forceinline__ uint32_t smem_u32(const void* p) {
    uint32_t a;
    asm("{ .reg .u64 t; cvta.to.shared.u64 t, %1; cvt.u32.u64 %0, t; }" : "=r"(a) : "l"(p));
    return a;
}

#define LDMX4(r0, r1, r2, r3, addr) \
    asm volatile("ldmatrix.sync.aligned.m8n8.x4.shared.b16 {%0,%1,%2,%3}, [%4];" \
        : "=r"(r0), "=r"(r1), "=r"(r2), "=r"(r3) : "r"(addr))

__device__ __forceinline__ void mma_f16(float* c, const uint32_t* a, uint32_t b0, uint32_t b1) {
    asm volatile(
        "mma.sync.aligned.m16n8k16.row.col.f32.f16.f16.f32 "
        "{%0,%1,%2,%3}, {%4,%5,%6,%7}, {%8,%9}, {%0,%1,%2,%3};"
        : "+f"(c[0]), "+f"(c[1]), "+f"(c[2]), "+f"(c[3])
        : "r"(a[0]), "r"(a[1]), "r"(a[2]), "r"(a[3]), "r"(b0), "r"(b1));
}

#define CP_COMMIT() asm volatile("cp.async.commit_group;" ::: "memory")
#define CP_WAIT2()  asm volatile("cp.async.wait_group 2;" ::: "memory")

// ---------------------------------------------------------------------------
// batch dtype detection (int32 vs int64 view; sorted-ness discriminates)
// ---------------------------------------------------------------------------
__global__ void k0_init() { g_is64 = 0; }
__global__ void k0_detect(const int* __restrict__ b32, int N) {
    int i = blockIdx.x * blockDim.x + threadIdx.x;
    if (i < N - 1) {
        int a = b32[i], b = b32[i + 1];
        if (a > b || a < 0 || b < 0) g_is64 = 1;
    }
}
__device__ __forceinline__ long long bval(const void* b, int i) {
    if (g_is64) return ((const long long*)b)[i];
    return (long long)((const int*)b)[i];
}

// ---------------------------------------------------------------------------
// W1a -> transposed fp16
// ---------------------------------------------------------------------------
__global__ void k_wt(const float* __restrict__ W1a) {
    int n = blockIdx.x, k = threadIdx.x;
    g_Wth[n * CC + k] = __float2half(W1a[k * CC + n]);
}

// ---------------------------------------------------------------------------
// K1: fused attention MLP, fp16 mma.sync, persistent CTAs, pipelined.
// B fragments in REGISTERS for the whole kernel (warp's n32 slice:
// 16 ks x 2 frags x 4 regs = 128). B smem needed only during prologue,
// overlaid with the 4-stage A32 cp.async ring.
// Per tile (32 nodes): wait stage -> convert fp32->fp16 swizzled ->
// prefetch stage+3 -> mma (m32 x n32/warp x k256, B from regs) ->
// relu.W2a epilogue -> cross-warp reduce -> sigmoid -> g_aw.
// ---------------------------------------------------------------------------
#define TILE_M    32
#define RING_OFF  0            // 4 x 32768 = 131072 (B fill region in prologue)
#define STG_BYTES 32768
#define A16_OFF   131072       // 16384
#define SB1_OFF   147456       // 1024
#define SW2_OFF   148480       // 1024
#define PBUF_OFF  149504       // 8*32 floats
#define K1_SMEM   150784

__device__ __forceinline__ void k1_load_stage(uint32_t sb, const float* __restrict__ x,
                                              int m0, int N, int s) {
    const int tid = threadIdx.x;
    #pragma unroll
    for (int u = 0; u < 8; ++u) {
        int idx = tid + u * 256;            // 2048 16B-chunks: 32 rows x 64 f4
        int row = idx >> 6, c4 = idx & 63;
        int node = m0 + row;
        const float* src = x + (size_t)(node < N ? node : 0) * CC + c4 * 4;
        uint32_t dst = sb + RING_OFF + s * STG_BYTES + row * 1024 + c4 * 16;
        uint32_t sz = (node < N) ? 16u : 0u;
        asm volatile("cp.async.cg.shared.global [%0], [%1], 16, %2;"
                     :: "r"(dst), "l"(src), "r"(sz));
    }
}

__global__ void __launch_bounds__(256, 1) k1_fp16(
    const float* __restrict__ x, const float* __restrict__ b1a,
    const float* __restrict__ W2a, const float* __restrict__ b2a,
    int N, int nTiles)
{
    extern __shared__ char sm[];
    const uint32_t sb = smem_u32(sm);
    float* sB1  = (float*)(sm + SB1_OFF);
    float* sW2  = (float*)(sm + SW2_OFF);
    float* pbuf = (float*)(sm + PBUF_OFF);

    const int tid  = threadIdx.x;
    const int lane = tid & 31;
    const int w    = tid >> 5;
    const int ncol0 = w * 32;

    sB1[tid] = b1a[tid];
    sW2[tid] = W2a[tid];
    const float b2 = b2a[0];

    // --- prologue: fill B smem (swizzled), hoist B frags to registers ---
    #pragma unroll 4
    for (int it = 0; it < 32; ++it) {
        int idx = tid + it * 256;          // 8192 16B-chunks (256 rows x 512B)
        int row = idx >> 5, c = idx & 31;
        uint4 v = *(const uint4*)(g_Wth + (size_t)row * CC + c * 8);
        *(uint4*)(sm + RING_OFF + row * 512 + ((c ^ (row & 7)) << 4)) = v;
    }
    __syncthreads();

    const int lrow   = lane & 15;
    const int lchunk = lane >> 4;
    const int qr = lane >> 2, qc = lane & 3;

    uint32_t breg[16][2][4];
    #pragma unroll
    for (int ks = 0; ks < 16; ++ks) {
        const int kc = ks * 2 + lchunk;
        #pragma unroll
        for (int bq = 0; bq < 2; ++bq) {
            int nr = ncol0 + bq * 16 + lrow;
            uint32_t ad = sb + RING_OFF + nr * 512 + ((kc ^ (nr & 7)) << 4);
            LDMX4(breg[ks][bq][0], breg[ks][bq][1], breg[ks][bq][2], breg[ks][bq][3], ad);
        }
    }
    __syncthreads();   // B region free -> becomes A ring

    // --- prime 3 ring stages ---
    #pragma unroll
    for (int j = 0; j < 3; ++j) {
        int tj = blockIdx.x + j * gridDim.x;
        if (tj < nTiles) k1_load_stage(sb, x, tj * TILE_M, N, j);
        CP_COMMIT();
    }

    int i = 0;
    for (int t = blockIdx.x; t < nTiles; t += gridDim.x, ++i) {
        const int s  = i & 3;
        const int m0 = t * TILE_M;

        CP_WAIT2();
        __syncthreads();          // stage s resident; pbuf free

        // convert A32[s] -> A16 (swizzled fp16)
        #pragma unroll
        for (int it = 0; it < 4; ++it) {
            int idx = tid + it * 256;      // 1024 fp16 16B-chunks: 32 rows x 32
            int row = idx >> 5, c = idx & 31;
            const float4* src = (const float4*)(sm + RING_OFF + s * STG_BYTES + row * 1024 + c * 32);
            float4 v0 = src[0], v1 = src[1];
            __half2 h0 = __floats2half2_rn(v0.x, v0.y), h1 = __floats2half2_rn(v0.z, v0.w);
            __half2 h2 = __floats2half2_rn(v1.x, v1.y), h3 = __floats2half2_rn(v1.z, v1.w);
            uint4 u;
            u.x = *(uint32_t*)&h0; u.y = *(uint32_t*)&h1;
            u.z = *(uint32_t*)&h2; u.w = *(uint32_t*)&h3;
            *(uint4*)(sm + A16_OFF + row * 512 + ((c ^ (row & 7)) << 4)) = u;
        }
        __syncthreads();          // A16 ready; A32[s] reusable

        // prefetch stage i+3 (overlaps mma below)
        {
            int tn = t + 3 * gridDim.x;
            if (tn < nTiles) k1_load_stage(sb, x, tn * TILE_M, N, (i + 3) & 3);
            CP_COMMIT();
        }

        // mma: warp computes m32 x n32 over k256; B from registers
        float acc[2][4][4];
        #pragma unroll
        for (int mt = 0; mt < 2; ++mt)
            #pragma unroll
            for (int j = 0; j < 4; ++j) {
                acc[mt][j][0] = 0.f; acc[mt][j][1] = 0.f;
                acc[mt][j][2] = 0.f; acc[mt][j][3] = 0.f;
            }
        #pragma unroll
        for (int ks = 0; ks < 16; ++ks) {
            const int kc = ks * 2 + lchunk;
            uint32_t a[2][4];
            #pragma unroll
            for (int mt = 0; mt < 2; ++mt) {
                int row = mt * 16 + lrow;
                uint32_t ad = sb + A16_OFF + row * 512 + ((kc ^ (row & 7)) << 4);
                LDMX4(a[mt][0], a[mt][1], a[mt][2], a[mt][3], ad);
            }
            #pragma unroll
            for (int mt = 0; mt < 2; ++mt)
                #pragma unroll
                for (int bq = 0; bq < 2; ++bq) {
                    mma_f16(acc[mt][2 * bq],     a[mt], breg[ks][bq][0], breg[ks][bq][2]);
                    mma_f16(acc[mt][2 * bq + 1], a[mt], breg[ks][bq][1], breg[ks][bq][3]);
                }
        }

        // epilogue: relu -> dot W2a (warp's n32 slice)
        float p[4] = {0.f, 0.f, 0.f, 0.f};   // rows qr, qr+8, 16+qr, 24+qr
        #pragma unroll
        for (int mt = 0; mt < 2; ++mt)
            #pragma unroll
            for (int j = 0; j < 4; ++j) {
                int col = ncol0 + j * 8 + qc * 2;
                float bA = sB1[col], bB = sB1[col + 1];
                float wA = sW2[col], wB = sW2[col + 1];
                p[mt * 2]     += fmaxf(acc[mt][j][0] + bA, 0.f) * wA
                               + fmaxf(acc[mt][j][1] + bB, 0.f) * wB;
                p[mt * 2 + 1] += fmaxf(acc[mt][j][2] + bA, 0.f) * wA
                               + fmaxf(acc[mt][j][3] + bB, 0.f) * wB;
            }
        #pragma unroll
        for (int j = 0; j < 4; ++j) {
            p[j] += __shfl_xor_sync(0xffffffffu, p[j], 1);
            p[j] += __shfl_xor_sync(0xffffffffu, p[j], 2);
        }
        if (qc == 0) {
            pbuf[w * 32 + qr]      = p[0];
            pbuf[w * 32 + qr + 8]  = p[1];
            pbuf[w * 32 + qr + 16] = p[2];
            pbuf[w * 32 + qr + 24] = p[3];
        }
        __syncthreads();
        if (tid < 32) {
            float ssum = 0.f;
            #pragma unroll
            for (int k = 0; k < 8; ++k) ssum += pbuf[k * 32 + tid];
            int node = m0 + tid;
            if (node < N) g_aw[node] = 1.f / (1.f + expf(-(ssum + b2)));
        }
    }
}

// ---------------------------------------------------------------------------
// K2: segment pooling. 512 threads = 64 float4-channel groups x 8 row lanes.
// batch sorted -> contiguous segments; binary-search bounds; no atomics.
// ---------------------------------------------------------------------------
__global__ void __launch_bounds__(512) k2_pool(
    const float* __restrict__ x, const void* __restrict__ batch, int N)
{
    const int g = blockIdx.x;
    __shared__ int sR[2];
    __shared__ float4 red[3][8][64];
    const int tid = threadIdx.x;
    const int cq  = tid & 63;
    const int r   = tid >> 6;     // 0..7

    if (tid == 0) {
        int lo = 0, hi = N;
        while (lo < hi) { int mid = (lo + hi) >> 1; if (bval(batch, mid) < (long long)g) lo = mid + 1; else hi = mid; }
        sR[0] = lo;
        hi = N;
        while (lo < hi) { int mid = (lo + hi) >> 1; if (bval(batch, mid) < (long long)g + 1) lo = mid + 1; else hi = mid; }
        sR[1] = lo;
    }
    __syncthreads();
    const int s = sR[0], e = sR[1];

    float4 sum = make_float4(0.f, 0.f, 0.f, 0.f);
    float4 att = make_float4(0.f, 0.f, 0.f, 0.f);
    float4 mx  = make_float4(-INFINITY, -INFINITY, -INFINITY, -INFINITY);

    for (int i = s + r; i < e; i += 8) {
        float4 v = ((const float4*)(x + (size_t)i * CC))[cq];
        float wt = g_aw[i];
        sum.x += v.x; sum.y += v.y; sum.z += v.z; sum.w += v.w;
        att.x = fmaf(v.x, wt, att.x); att.y = fmaf(v.y, wt, att.y);
        att.z = fmaf(v.z, wt, att.z); att.w = fmaf(v.w, wt, att.w);
        mx.x = fmaxf(mx.x, v.x); mx.y = fmaxf(mx.y, v.y);
        mx.z = fmaxf(mx.z, v.z); mx.w = fmaxf(mx.w, v.w);
    }
    red[0][r][cq] = sum; red[1][r][cq] = att; red[2][r][cq] = mx;
    __syncthreads();

    if (r == 0) {
        #pragma unroll
        for (int k = 1; k < 8; ++k) {
            float4 a = red[0][k][cq], b = red[1][k][cq], m = red[2][k][cq];
            sum.x += a.x; sum.y += a.y; sum.z += a.z; sum.w += a.w;
            att.x += b.x; att.y += b.y; att.z += b.z; att.w += b.w;
            mx.x = fmaxf(mx.x, m.x); mx.y = fmaxf(mx.y, m.y);
            mx.z = fmaxf(mx.z, m.z); mx.w = fmaxf(mx.w, m.w);
        }
        float inv = 1.f / fmaxf((float)(e - s), 1.f);
        float4 mean = make_float4(sum.x * inv, sum.y * inv, sum.z * inv, sum.w * inv);
        float4 mxo = (e > s) ? mx : make_float4(0.f, 0.f, 0.f, 0.f);
        float* comb = g_comb + (size_t)g * (3 * CC);
        ((float4*)(comb))[cq]          = att;
        ((float4*)(comb + CC))[cq]     = mean;
        ((float4*)(comb + 2 * CC))[cq] = mxo;
    }
}

// ---------------------------------------------------------------------------
// K3: fp32 tiled GEMM with bias (+optional relu). 64x64 tile, 256 threads.
// ---------------------------------------------------------------------------
template <bool RELU>
__global__ void __launch_bounds__(256) k3_gemm(
    const float* __restrict__ A, const float* __restrict__ B,
    const float* __restrict__ bias, float* __restrict__ Out,
    int M, int K, int Nn)
{
    __shared__ float sA[16][68];
    __shared__ float sB[16][68];
    const int t  = threadIdx.x;
    const int tx = t & 15, ty = t >> 4;
    const int m0 = blockIdx.y * 64, n0 = blockIdx.x * 64;
    float acc[4][4] = {};

    for (int kt = 0; kt < K; kt += 16) {
        #pragma unroll
        for (int i = 0; i < 4; ++i) {
            int idx = t + i * 256;
            int m = idx >> 4, k = idx & 15;
            sA[k][m] = A[(size_t)(m0 + m) * K + kt + k];
        }
        #pragma unroll
        for (int i = 0; i < 4; ++i) {
            int idx = t + i * 256;
            int k = idx >> 6, n = idx & 63;
            sB[k][n] = B[(size_t)(kt + k) * Nn + n0 + n];
        }
        __syncthreads();
        #pragma unroll
        for (int kk = 0; kk < 16; ++kk) {
            float4 a4 = *(const float4*)&sA[kk][ty * 4];
            float4 b4 = *(const float4*)&sB[kk][tx * 4];
            float av[4] = {a4.x, a4.y, a4.z, a4.w};
            float bv[4] = {b4.x, b4.y, b4.z, b4.w};
            #pragma unroll
            for (int i = 0; i < 4; ++i)
                #pragma unroll
                for (int j = 0; j < 4; ++j)
                    acc[i][j] = fmaf(av[i], bv[j], acc[i][j]);
        }
        __syncthreads();
    }

    #pragma unroll
    for (int i = 0; i < 4; ++i) {
        int m = m0 + ty * 4 + i;
        #pragma unroll
        for (int j = 0; j < 4; ++j) {
            int n = n0 + tx * 4 + j;
            float v = acc[i][j] + bias[n];
            if (RELU) v = fmaxf(v, 0.f);
            Out[(size_t)m * Nn + n] = v;
        }
    }
}

// ---------------------------------------------------------------------------
// launch
// ---------------------------------------------------------------------------
extern "C" void kernel_launch(void* const* d_in, const int* in_sizes, int n_in,
                              void* d_out, int out_size)
{
    const float* x     = (const float*)d_in[0];
    const void*  batch = d_in[1];
    const float* W1a   = (const float*)d_in[2];
    const float* b1a   = (const float*)d_in[3];
    const float* W2a   = (const float*)d_in[4];
    const float* b2a   = (const float*)d_in[5];
    const float* W1f   = (const float*)d_in[6];
    const float* b1f   = (const float*)d_in[7];
    const float* W2f   = (const float*)d_in[8];
    const float* b2f   = (const float*)d_in[9];
    float* out = (float*)d_out;

    const int N = in_sizes[0] / CC;
    const int G = out_size / CC;

    float *comb_ptr = nullptr, *hid_ptr = nullptr;
    cudaGetSymbolAddress((void**)&comb_ptr, g_comb);
    cudaGetSymbolAddress((void**)&hid_ptr, g_hidden);

    cudaFuncSetAttribute(k1_fp16, cudaFuncAttributeMaxDynamicSharedMemorySize, K1_SMEM);

    k0_init<<<1, 1>>>();
    k0_detect<<<(N + 255) / 256, 256>>>((const int*)batch, N);
    k_wt<<<CC, CC>>>(W1a);

    const int nTiles = (N + TILE_M - 1) / TILE_M;
    const int grid = nTiles < 148 ? nTiles : 148;
    k1_fp16<<<grid, 256, K1_SMEM>>>(x, b1a, W2a, b2a, N, nTiles);
    k2_pool<<<G, 512>>>(x, batch, N);
    k3_gemm<true ><<<dim3(CC / 64, G / 64), 256>>>(comb_ptr, W1f, b1f, hid_ptr, G, 3 * CC, CC);
    k3_gemm<false><<<dim3(CC / 64, G / 64), 256>>>(hid_ptr,  W2f, b2f, out,     G, CC,     CC);
}